// round 5
// baseline (speedup 1.0000x reference)
#include <cuda_runtime.h>
#include <math.h>

#define HW   61440
#define TILE 64
#define LDA  66     // transposed activation stride [feat][pixel]; even (8B pairs), 2-way conflict max
#define NTHR 512

// Transposed weights, K-major: Wt_l[k*N + n] = W_l[n*ldw + k]
#define O0 0        // 64 x 64
#define O1 4096     // 64 x 64
#define O2 8192     // 64 x 256
#define O3 24576    // 256 x 256
#define O4 90112    // 256 x 256
#define O5 155648   // 256 x 64
#define WT_TOTAL 172032
__device__ float g_wt[WT_TOTAL];

typedef unsigned long long u64;

__device__ __forceinline__ u64 pack_dup(float w) {
    u64 r; asm("mov.b64 %0, {%1,%2};" : "=l"(r) : "f"(w), "f"(w)); return r;
}
__device__ __forceinline__ void ffma2(u64 &d, u64 a, u64 b) {
    asm("fma.rn.f32x2 %0, %1, %2, %0;" : "+l"(d) : "l"(a), "l"(b));
}
__device__ __forceinline__ void unpack2(u64 v, float &lo, float &hi) {
    asm("mov.b64 {%0,%1}, %2;" : "=f"(lo), "=f"(hi) : "l"(v));
}

__global__ void transpose_weights_kernel(
    const float* __restrict__ w0, const float* __restrict__ w1,
    const float* __restrict__ w2, const float* __restrict__ w3,
    const float* __restrict__ w4, const float* __restrict__ w5)
{
    int i = blockIdx.x * blockDim.x + threadIdx.x;
    if (i >= WT_TOTAL) return;
    float v; int j;
    if      (i < O1)      { j = i - O0; v = w0[(j & 63)  * 65  + (j >> 6)]; }
    else if (i < O2)      { j = i - O1; v = w1[(j & 63)  * 64  + (j >> 6)]; }
    else if (i < O3)      { j = i - O2; v = w2[(j & 255) * 64  + (j >> 8)]; }
    else if (i < O4)      { j = i - O3; v = w3[(j & 255) * 256 + (j >> 8)]; }
    else if (i < O5)      { j = i - O4; v = w4[(j & 255) * 256 + (j >> 8)]; }
    else                  { j = i - O5; v = w5[(j & 63)  * 256 + (j >> 6)]; }
    g_wt[i] = v;
}

// Layer: Aout^T[N][64] = f(W[NxK] @ Ain^T[K][64] + bias)
// A buffers TRANSPOSED: [feature][pixel], stride LDA (shared memory).
// Weights read straight from L1/L2 via coalesced LDG from g_wt (K-major).
// Block (32,16): rg=ty&7 -> pixel rows rg*8..+7 (4 f32x2 pairs);
//                cg=ty>>3 -> column half; cols = tx + 32*(cg*CPT + c), CPT=N/64.
template<int K, int N, bool SIN, bool L0>
__device__ __forceinline__ void layer_gemm(
    const float* __restrict__ Ain, float* __restrict__ Aout,
    const float* __restrict__ Wt,            // g_wt + layer offset, K-major [K][N]
    const float* __restrict__ bias,
    const float* __restrict__ wt_time, float tval,
    int tx, int ty)
{
    constexpr int CPT = N / 64;   // cols per thread (1 or 4)
    u64 acc[4][CPT];
    #pragma unroll
    for (int i = 0; i < 4; ++i)
        #pragma unroll
        for (int c = 0; c < CPT; ++c) acc[i][c] = 0ULL;

    const int rbase = (ty & 7) * 8;
    const int cg    = ty >> 3;
    const int cbase = tx + 32 * (cg * CPT);

    const float* wk = Wt + cbase;

    #pragma unroll 2
    for (int k = 0; k < K; ++k) {
        const float* arow = Ain + k * LDA + rbase;
        u64 a2[4];
        #pragma unroll
        for (int i = 0; i < 4; ++i)
            a2[i] = *(const u64*)(arow + 2 * i);          // broadcast LDS.64
        #pragma unroll
        for (int c = 0; c < CPT; ++c) {
            u64 w2 = pack_dup(__ldg(wk + 32 * c));        // coalesced LDG.32, L1-hot
            #pragma unroll
            for (int i = 0; i < 4; ++i)
                ffma2(acc[i][c], a2[i], w2);
        }
        wk += N;
    }

    // Epilogue: bias (+ folded time for layer 0), sin(30x) on hidden layers.
    #pragma unroll
    for (int c = 0; c < CPT; ++c) {
        int col = cbase + 32 * c;
        float bb = bias[col];
        if constexpr (L0) bb += tval * wt_time[col * 65];   // W0[col][64] * t
        #pragma unroll
        for (int i = 0; i < 4; ++i) {
            float lo, hi;
            unpack2(acc[i][c], lo, hi);
            lo += bb; hi += bb;
            if constexpr (SIN) { lo = sinf(30.0f * lo); hi = sinf(30.0f * hi); }
            float2 v = make_float2(lo, hi);
            *(float2*)(Aout + col * LDA + rbase + 2 * i) = v;  // ~2-way conflict
        }
    }
    __syncthreads();
}

extern __shared__ float smem[];

__global__ __launch_bounds__(NTHR, 1)
void liif_siren_kernel(
    const float* __restrict__ feat, const float* __restrict__ times,
    const float* __restrict__ w0, const float* __restrict__ b0,
    const float* __restrict__ b1, const float* __restrict__ b2,
    const float* __restrict__ b3, const float* __restrict__ b4,
    const float* __restrict__ b5,
    float* __restrict__ out)
{
    float* A0 = smem;                 // 256 x LDA ([feat][pixel])
    float* A1 = A0 + 256 * LDA;       // 256 x LDA

    const int tx = threadIdx.x, ty = threadIdx.y;
    const int tid = ty * 32 + tx;
    const int p0 = blockIdx.x * TILE;
    const int b  = blockIdx.y;
    const int t  = blockIdx.z;
    const float tval = times[t];

    // Identity gather, transposed store: A0[c][p] = feat[b][c][p0+p].
    for (int e = tid; e < TILE * 64; e += NTHR) {
        int p = e & 63, c = e >> 6;
        A0[c * LDA + p] = feat[(b * 64 + c) * HW + p0 + p];
    }
    __syncthreads();

    layer_gemm< 64,  64, true,  true >(A0, A1, g_wt + O0, b0, w0 + 64, tval, tx, ty);
    layer_gemm< 64,  64, true,  false>(A1, A0, g_wt + O1, b1, nullptr, 0.f,  tx, ty);
    layer_gemm< 64, 256, true,  false>(A0, A1, g_wt + O2, b2, nullptr, 0.f,  tx, ty);
    layer_gemm<256, 256, true,  false>(A1, A0, g_wt + O3, b3, nullptr, 0.f,  tx, ty);
    layer_gemm<256, 256, true,  false>(A0, A1, g_wt + O4, b4, nullptr, 0.f,  tx, ty);
    layer_gemm<256,  64, false, false>(A1, A0, g_wt + O5, b5, nullptr, 0.f,  tx, ty);

    // out[t][b][o][p0+p], result in A0 as [o][p].
    for (int e = tid; e < TILE * 64; e += NTHR) {
        int p = e & 63, o = e >> 6;
        out[(size_t)((t * 2 + b) * 64 + o) * HW + p0 + p] = A0[o * LDA + p];
    }
}

extern "C" void kernel_launch(void* const* d_in, const int* in_sizes, int n_in,
                              void* d_out, int out_size) {
    const float* feat  = (const float*)d_in[0];
    const float* times = (const float*)d_in[1];
    const float* w0 = (const float*)d_in[2];
    const float* b0 = (const float*)d_in[3];
    const float* w1 = (const float*)d_in[4];
    const float* b1 = (const float*)d_in[5];
    const float* w2 = (const float*)d_in[6];
    const float* b2 = (const float*)d_in[7];
    const float* w3 = (const float*)d_in[8];
    const float* b3 = (const float*)d_in[9];
    const float* w4 = (const float*)d_in[10];
    const float* b4 = (const float*)d_in[11];
    const float* w5 = (const float*)d_in[12];
    const float* b5 = (const float*)d_in[13];
    float* out = (float*)d_out;

    transpose_weights_kernel<<<(WT_TOTAL + 255) / 256, 256>>>(w0, w1, w2, w3, w4, w5);

    const size_t smem_bytes = (size_t)(2 * 256 * LDA) * sizeof(float); // 135168 B
    cudaFuncSetAttribute(liif_siren_kernel,
                         cudaFuncAttributeMaxDynamicSharedMemorySize, (int)smem_bytes);

    dim3 grid(HW / TILE, 2, 3);   // 5760 blocks
    dim3 block(32, 16, 1);
    liif_siren_kernel<<<grid, block, smem_bytes>>>(
        feat, times, w0, b0, b1, b2, b3, b4, b5, out);
}

// round 7
// speedup vs baseline: 2.4460x; 2.4460x over previous
#include <cuda_runtime.h>
#include <cuda_bf16.h>
#include <math.h>
#include <stdint.h>

#define HW    61440
#define MTILE 128
#define NTHR  512

typedef unsigned int u32;

// Pre-split (bf16 hi/lo), pre-padded weights. Per layer, per K64-chunk:
// [hi image: N rows x 72 halves][lo image: N x 72], row stride 144B.
// Layer bases (bytes): L0 0, L1 18432, L2 36864, L3 110592, L4 405504, L5 700416.
__device__ __align__(16) unsigned char g_wb[774144];

// smem layout (bytes):
//   0      A_hi image (max 128 x 264 halves = 67584)
//   67584  A_lo image (67584)
//   135168 W chunk (hi+lo, max 256*288 = 73728)
//   208896 bias[960] (3840)
#define SM_W    135168
#define SM_BIAS 208896
#define SM_TOT  212736
#define ALO_OFF 67584

__device__ __forceinline__ u32 smem_u32(const void* p) {
    u32 a; asm("{ .reg .u64 t; cvta.to.shared.u64 t, %1; cvt.u32.u64 %0, t; }"
               : "=r"(a) : "l"(p)); return a;
}
__device__ __forceinline__ void ldsm4(unsigned* r, u32 addr) {
    asm volatile("ldmatrix.sync.aligned.m8n8.x4.shared.b16 {%0,%1,%2,%3}, [%4];"
        : "=r"(r[0]), "=r"(r[1]), "=r"(r[2]), "=r"(r[3]) : "r"(addr));
}
__device__ __forceinline__ void mma_bf16(float* d, const unsigned* a, unsigned b0, unsigned b1) {
    asm volatile("mma.sync.aligned.m16n8k16.row.col.f32.bf16.bf16.f32 "
        "{%0,%1,%2,%3}, {%4,%5,%6,%7}, {%8,%9}, {%0,%1,%2,%3};"
        : "+f"(d[0]), "+f"(d[1]), "+f"(d[2]), "+f"(d[3])
        : "r"(a[0]), "r"(a[1]), "r"(a[2]), "r"(a[3]), "r"(b0), "r"(b1));
}
__device__ __forceinline__ u32 pack_bf2(float v0, float v1) {
    __nv_bfloat162 h = __floats2bfloat162_rn(v0, v1);
    return *(u32*)&h;
}

// ---------- weight prep ----------
__global__ void prep_weights(
    const float* __restrict__ w0, const float* __restrict__ w1,
    const float* __restrict__ w2, const float* __restrict__ w3,
    const float* __restrict__ w4, const float* __restrict__ w5)
{
    int i = blockIdx.x * blockDim.x + threadIdx.x;
    if (i >= 172032) return;
    const float* w; int j, K, N, ldw; u32 base;
    if      (i < 4096)   { j = i;          w = w0; K = 64;  N = 64;  ldw = 65;  base = 0; }
    else if (i < 8192)   { j = i - 4096;   w = w1; K = 64;  N = 64;  ldw = 64;  base = 18432; }
    else if (i < 24576)  { j = i - 8192;   w = w2; K = 64;  N = 256; ldw = 64;  base = 36864; }
    else if (i < 90112)  { j = i - 24576;  w = w3; K = 256; N = 256; ldw = 256; base = 110592; }
    else if (i < 155648) { j = i - 90112;  w = w4; K = 256; N = 256; ldw = 256; base = 405504; }
    else                 { j = i - 155648; w = w5; K = 256; N = 64;  ldw = 256; base = 700416; }
    int n = j / K, k = j % K;
    float v = w[n * ldw + k];
    __nv_bfloat16 h = __float2bfloat16(v);
    __nv_bfloat16 lo = __float2bfloat16(v - __bfloat162float(h));
    u32 dst = base + (u32)(k >> 6) * ((u32)N * 288u) + (u32)n * 144u + (u32)(k & 63) * 2u;
    *(__nv_bfloat16*)(g_wb + dst)            = h;
    *(__nv_bfloat16*)(g_wb + dst + N * 144)  = lo;
}

// ---------- per-layer GEMM ----------
// D[128 x N] = A[128 x K] @ W^T, 3-term bf16 split, in-place activation update.
// 16 warps: wr=wid&3 -> m0=wr*32 (2 m16 tiles); wc=wid>>2 -> n0=wc*(N/4).
template<int K, int N, bool SIN, bool LAST>
__device__ __forceinline__ void layer_mma(
    unsigned char* smem, u32 sb, u32 wbase, const float* bias_l, int tid)
{
    constexpr int Sin  = K + 8;       // halves
    constexpr int Sout = N + 8;
    constexpr int NC   = N / 64;      // n16 chunks per warp
    constexpr int CH   = K / 64;      // K64 chunks

    const int lane = tid & 31, wid = tid >> 5;
    const int m0 = (wid & 3) * 32;
    const int n0 = (wid >> 2) * (N / 4);

    float acc[2][N / 32][4];
    #pragma unroll
    for (int mt = 0; mt < 2; ++mt)
        #pragma unroll
        for (int j = 0; j < N / 32; ++j)
            #pragma unroll
            for (int q = 0; q < 4; ++q) acc[mt][j][q] = 0.0f;

    const int koff8 = (lane & 16) ? 8 : 0;
    const u32 AHI = sb;
    const u32 ALO = sb + ALO_OFF;
    const u32 aoff = (u32)(((m0 + (lane & 15)) * Sin + koff8) * 2);
    const u32 WHI = sb + SM_W;
    const u32 WLO = WHI + (u32)N * 144u;
    const u32 boff = (u32)(((n0 + (lane & 15)) * 72 + koff8) * 2);

    for (int c = 0; c < CH; ++c) {
        __syncthreads();   // prior chunk fully consumed / prev epilogue visible
        {   // stage W chunk (straight copy of prebuilt image)
            const uint4* src = (const uint4*)(g_wb + wbase + (size_t)c * (N * 288));
            uint4* dst = (uint4*)(smem + SM_W);
            #pragma unroll 4
            for (int i = tid; i < N * 288 / 16; i += NTHR) dst[i] = src[i];
        }
        __syncthreads();

        #pragma unroll
        for (int kk = 0; kk < 4; ++kk) {
            const int kg = c * 4 + kk;
            unsigned ah[2][4], al[2][4];
            ldsm4(ah[0], AHI + aoff + kg * 32);
            ldsm4(ah[1], AHI + aoff + 16 * Sin * 2 + kg * 32);
            ldsm4(al[0], ALO + aoff + kg * 32);
            ldsm4(al[1], ALO + aoff + 16 * Sin * 2 + kg * 32);
            #pragma unroll
            for (int nc = 0; nc < NC; ++nc) {
                unsigned bh[4], bl[4];
                ldsm4(bh, WHI + boff + nc * (16 * 144) + kk * 32);
                ldsm4(bl, WLO + boff + nc * (16 * 144) + kk * 32);
                #pragma unroll
                for (int mt = 0; mt < 2; ++mt) {
                    mma_bf16(acc[mt][nc * 2 + 0], ah[mt], bh[0], bh[2]);
                    mma_bf16(acc[mt][nc * 2 + 1], ah[mt], bh[1], bh[3]);
                    mma_bf16(acc[mt][nc * 2 + 0], al[mt], bh[0], bh[2]);
                    mma_bf16(acc[mt][nc * 2 + 1], al[mt], bh[1], bh[3]);
                    mma_bf16(acc[mt][nc * 2 + 0], ah[mt], bl[0], bl[2]);
                    mma_bf16(acc[mt][nc * 2 + 1], ah[mt], bl[1], bl[3]);
                }
            }
        }
    }
    __syncthreads();   // all MMAs done (accs in regs) before in-place writeback

    const int r = lane >> 2, cq = lane & 3;
    #pragma unroll
    for (int mt = 0; mt < 2; ++mt) {
        #pragma unroll
        for (int j = 0; j < N / 32; ++j) {
            const int col = n0 + j * 8 + cq * 2;
            const float b0v = bias_l[col], b1v = bias_l[col + 1];
            const int row0 = m0 + mt * 16 + r;
            float v00 = acc[mt][j][0] + b0v, v01 = acc[mt][j][1] + b1v;
            float v10 = acc[mt][j][2] + b0v, v11 = acc[mt][j][3] + b1v;
            if constexpr (SIN) {
                v00 = sinf(30.0f * v00); v01 = sinf(30.0f * v01);
                v10 = sinf(30.0f * v10); v11 = sinf(30.0f * v11);
            }
            if constexpr (!LAST) {
                __nv_bfloat162 h0 = __floats2bfloat162_rn(v00, v01);
                __nv_bfloat162 h1 = __floats2bfloat162_rn(v10, v11);
                float l00 = v00 - __bfloat162float(__low2bfloat16(h0));
                float l01 = v01 - __bfloat162float(__high2bfloat16(h0));
                float l10 = v10 - __bfloat162float(__low2bfloat16(h1));
                float l11 = v11 - __bfloat162float(__high2bfloat16(h1));
                *(u32*)(smem + 2 * (row0 * Sout + col))                 = *(u32*)&h0;
                *(u32*)(smem + 2 * ((row0 + 8) * Sout + col))           = *(u32*)&h1;
                *(u32*)(smem + ALO_OFF + 2 * (row0 * Sout + col))       = pack_bf2(l00, l01);
                *(u32*)(smem + ALO_OFF + 2 * ((row0 + 8) * Sout + col)) = pack_bf2(l10, l11);
            } else {
                float* smf = (float*)smem;   // [n][128 pixels] fp32
                smf[col * 128 + row0]           = v00;
                smf[(col + 1) * 128 + row0]     = v01;
                smf[col * 128 + row0 + 8]       = v10;
                smf[(col + 1) * 128 + row0 + 8] = v11;
            }
        }
    }
}

extern __shared__ unsigned char smem[];

__global__ __launch_bounds__(NTHR, 1)
void liif_mma_kernel(
    const float* __restrict__ feat, const float* __restrict__ times,
    const float* __restrict__ w0,
    const float* __restrict__ b0, const float* __restrict__ b1,
    const float* __restrict__ b2, const float* __restrict__ b3,
    const float* __restrict__ b4, const float* __restrict__ b5,
    float* __restrict__ out)
{
    const int tid = threadIdx.x;
    const int p0 = blockIdx.x * MTILE;
    const int bb = blockIdx.y;
    const int tt = blockIdx.z;
    const u32 sb = smem_u32(smem);
    const float tval = times[tt];

    // biases (time folded into b0)
    float* sbias = (float*)(smem + SM_BIAS);
    for (int i = tid; i < 960; i += NTHR) {
        float v;
        if      (i < 64)  v = b0[i] + tval * w0[i * 65 + 64];
        else if (i < 128) v = b1[i - 64];
        else if (i < 384) v = b2[i - 128];
        else if (i < 640) v = b3[i - 384];
        else if (i < 896) v = b4[i - 640];
        else              v = b5[i - 896];
        sbias[i] = v;
    }

    // feat -> A hi/lo images, stride 72 halves (identity gather)
    for (int e = tid; e < MTILE * 64; e += NTHR) {
        int c = e >> 7, p = e & 127;
        float v = feat[(size_t)(bb * 64 + c) * HW + p0 + p];
        __nv_bfloat16 h = __float2bfloat16(v);
        __nv_bfloat16 lo = __float2bfloat16(v - __bfloat162float(h));
        *(__nv_bfloat16*)(smem + 2 * (p * 72 + c))           = h;
        *(__nv_bfloat16*)(smem + ALO_OFF + 2 * (p * 72 + c)) = lo;
    }
    // (first layer_mma begins with __syncthreads())

    layer_mma< 64,  64, true,  false>(smem, sb, 0,      sbias,       tid);
    layer_mma< 64,  64, true,  false>(smem, sb, 18432,  sbias + 64,  tid);
    layer_mma< 64, 256, true,  false>(smem, sb, 36864,  sbias + 128, tid);
    layer_mma<256, 256, true,  false>(smem, sb, 110592, sbias + 384, tid);
    layer_mma<256, 256, true,  false>(smem, sb, 405504, sbias + 640, tid);
    layer_mma<256,  64, false, true >(smem, sb, 700416, sbias + 896, tid);

    __syncthreads();
    // coalesced store: out[(tt*2+bb)*64 + n][p0 + p]
    float* smf = (float*)smem;
    float* gout = out + (size_t)(tt * 2 + bb) * 64 * HW;
    for (int e = tid; e < 64 * 128; e += NTHR) {
        int n = e >> 7, p = e & 127;
        gout[(size_t)n * HW + p0 + p] = smf[n * 128 + p];
    }
}

extern "C" void kernel_launch(void* const* d_in, const int* in_sizes, int n_in,
                              void* d_out, int out_size) {
    const float* feat  = (const float*)d_in[0];
    const float* times = (const float*)d_in[1];
    const float* w0 = (const float*)d_in[2];
    const float* b0 = (const float*)d_in[3];
    const float* w1 = (const float*)d_in[4];
    const float* b1 = (const float*)d_in[5];
    const float* w2 = (const float*)d_in[6];
    const float* b2 = (const float*)d_in[7];
    const float* w3 = (const float*)d_in[8];
    const float* b3 = (const float*)d_in[9];
    const float* w4 = (const float*)d_in[10];
    const float* b4 = (const float*)d_in[11];
    const float* w5 = (const float*)d_in[12];
    const float* b5 = (const float*)d_in[13];
    float* out = (float*)d_out;

    prep_weights<<<(172032 + 255) / 256, 256>>>(w0, w1, w2, w3, w4, w5);

    cudaFuncSetAttribute(liif_mma_kernel,
                         cudaFuncAttributeMaxDynamicSharedMemorySize, SM_TOT);
    dim3 grid(HW / MTILE, 2, 3);   // 480 x 2 x 3 = 2880 CTAs
    liif_mma_kernel<<<grid, NTHR, SM_TOT>>>(
        feat, times, w0, b0, b1, b2, b3, b4, b5, out);
}

// round 8
// speedup vs baseline: 2.6637x; 1.0890x over previous
#include <cuda_runtime.h>
#include <cuda_bf16.h>
#include <math.h>
#include <stdint.h>

#define HW    61440
#define MTILE 128
#define NTHR  512

typedef unsigned int u32;

// Pre-split (bf16 hi/lo), pre-padded weights. Per layer, per K64-chunk:
// [hi image: N x 72 halves][lo image: N x 72], row stride 144B. Layers contiguous:
// L0 0, L1 18432, L2 36864, L3 110592, L4 405504, L5 700416, end 774144.
// +36864 pad so fixed-window prefetch never over-reads.
__device__ __align__(16) unsigned char g_wb[811008];

// smem layout (bytes):
//   0      A_hi image (max 128 x 264 halves = 67584)
//   67584  A_lo image (67584)
//   135168 W stage buffers: 2 x 36864
//   208896 bias[960]
#define SM_W    135168
#define WBUF    36864
#define SM_BIAS 208896
#define SM_TOT  212736
#define ALO_OFF 67584

__device__ __forceinline__ u32 smem_u32(const void* p) {
    u32 a; asm("{ .reg .u64 t; cvta.to.shared.u64 t, %1; cvt.u32.u64 %0, t; }"
               : "=r"(a) : "l"(p)); return a;
}
__device__ __forceinline__ void ldsm4(unsigned* r, u32 addr) {
    asm volatile("ldmatrix.sync.aligned.m8n8.x4.shared.b16 {%0,%1,%2,%3}, [%4];"
        : "=r"(r[0]), "=r"(r[1]), "=r"(r[2]), "=r"(r[3]) : "r"(addr));
}
__device__ __forceinline__ void mma_bf16(float* d, const unsigned* a, unsigned b0, unsigned b1) {
    asm volatile("mma.sync.aligned.m16n8k16.row.col.f32.bf16.bf16.f32 "
        "{%0,%1,%2,%3}, {%4,%5,%6,%7}, {%8,%9}, {%0,%1,%2,%3};"
        : "+f"(d[0]), "+f"(d[1]), "+f"(d[2]), "+f"(d[3])
        : "r"(a[0]), "r"(a[1]), "r"(a[2]), "r"(a[3]), "r"(b0), "r"(b1));
}
__device__ __forceinline__ void cp16(u32 dst, const void* src) {
    asm volatile("cp.async.cg.shared.global [%0], [%1], 16;" :: "r"(dst), "l"(src));
}
#define CP_COMMIT() asm volatile("cp.async.commit_group;" ::: "memory")
#define CP_WAIT0()  asm volatile("cp.async.wait_group 0;" ::: "memory")

__device__ __forceinline__ u32 pack_bf2(float v0, float v1) {
    __nv_bfloat162 h = __floats2bfloat162_rn(v0, v1);
    return *(u32*)&h;
}

// ---------- weight prep ----------
__global__ void prep_weights(
    const float* __restrict__ w0, const float* __restrict__ w1,
    const float* __restrict__ w2, const float* __restrict__ w3,
    const float* __restrict__ w4, const float* __restrict__ w5)
{
    int i = blockIdx.x * blockDim.x + threadIdx.x;
    if (i >= 172032) return;
    const float* w; int j, K, N, ldw; u32 base;
    if      (i < 4096)   { j = i;          w = w0; K = 64;  N = 64;  ldw = 65;  base = 0; }
    else if (i < 8192)   { j = i - 4096;   w = w1; K = 64;  N = 64;  ldw = 64;  base = 18432; }
    else if (i < 24576)  { j = i - 8192;   w = w2; K = 64;  N = 256; ldw = 64;  base = 36864; }
    else if (i < 90112)  { j = i - 24576;  w = w3; K = 256; N = 256; ldw = 256; base = 110592; }
    else if (i < 155648) { j = i - 90112;  w = w4; K = 256; N = 256; ldw = 256; base = 405504; }
    else                 { j = i - 155648; w = w5; K = 256; N = 64;  ldw = 256; base = 700416; }
    int n = j / K, k = j % K;
    float v = w[n * ldw + k];
    __nv_bfloat16 h = __float2bfloat16(v);
    __nv_bfloat16 lo = __float2bfloat16(v - __bfloat162float(h));
    u32 dst = base + (u32)(k >> 6) * ((u32)N * 288u) + (u32)n * 144u + (u32)(k & 63) * 2u;
    *(__nv_bfloat16*)(g_wb + dst)            = h;
    *(__nv_bfloat16*)(g_wb + dst + N * 144)  = lo;
}

// ---------- per-layer GEMM, 2-deep cp.async weight pipeline ----------
// D[128 x N] = A[128 x K] @ W^T, 3-term bf16 split, in-place activation update.
// Stages: per K64-chunk, stage0 = hi image (terms AhBh + AlBh), stage1 = lo (AhBl).
// Per stage: wait prev copy -> sync -> issue next copy -> compute.
template<int K, int N, bool SIN, bool LAST, int NEXTB>
__device__ __forceinline__ void layer_mma(
    unsigned char* smem, u32 sb, u32 wbase, const float* bias_l, int tid)
{
    constexpr int Sin  = K + 8;        // halves
    constexpr int Sout = N + 8;
    constexpr int NC   = N / 64;       // n16 chunks per warp
    constexpr int NST  = (K / 64) * 2; // stages
    constexpr int STB  = N * 144;      // stage bytes

    const int lane = tid & 31, wid = tid >> 5;
    const int m0 = (wid & 3) * 32;
    const int n0 = (wid >> 2) * (N / 4);

    float acc[2][N / 32][4];
    #pragma unroll
    for (int mt = 0; mt < 2; ++mt)
        #pragma unroll
        for (int j = 0; j < N / 32; ++j)
            #pragma unroll
            for (int q = 0; q < 4; ++q) acc[mt][j][q] = 0.0f;

    const int koff8 = (lane & 16) ? 8 : 0;
    const u32 AHI = sb;
    const u32 ALO = sb + ALO_OFF;
    const u32 aoff = (u32)(((m0 + (lane & 15)) * Sin + koff8) * 2);
    const u32 boff = (u32)(((n0 + (lane & 15)) * 72 + koff8) * 2);

    #pragma unroll
    for (int st = 0; st < NST; ++st) {
        CP_WAIT0();            // stage st data arrived
        __syncthreads();       // visible to all; all warps past stage st-1 compute

        // issue prefetch of next stage (or next layer's first stage)
        {
            constexpr int last = 0;   // silence unused warnings pattern
            (void)last;
            const int nb = (st + 1 < NST) ? STB : NEXTB;
            if (nb > 0) {
                const unsigned char* src = g_wb + wbase + (size_t)(st + 1) * STB;
                u32 dst = sb + SM_W + (u32)(((st + 1) & 1) * WBUF);
                for (int i = tid * 16; i < nb; i += NTHR * 16)
                    cp16(dst + i, src + i);
            }
            CP_COMMIT();
        }

        const u32 WB = sb + SM_W + (u32)((st & 1) * WBUF);
        const int c = st >> 1;

        if ((st & 1) == 0) {
            // hi image: acc += Ah*Bh + Al*Bh
            #pragma unroll
            for (int kk = 0; kk < 4; ++kk) {
                const int kg = c * 4 + kk;
                unsigned ah[2][4], al[2][4];
                ldsm4(ah[0], AHI + aoff + kg * 32);
                ldsm4(ah[1], AHI + aoff + 16 * Sin * 2 + kg * 32);
                ldsm4(al[0], ALO + aoff + kg * 32);
                ldsm4(al[1], ALO + aoff + 16 * Sin * 2 + kg * 32);
                #pragma unroll
                for (int nc = 0; nc < NC; ++nc) {
                    unsigned bh[4];
                    ldsm4(bh, WB + boff + nc * (16 * 144) + kk * 32);
                    #pragma unroll
                    for (int mt = 0; mt < 2; ++mt) {
                        mma_bf16(acc[mt][nc * 2 + 0], ah[mt], bh[0], bh[2]);
                        mma_bf16(acc[mt][nc * 2 + 1], ah[mt], bh[1], bh[3]);
                        mma_bf16(acc[mt][nc * 2 + 0], al[mt], bh[0], bh[2]);
                        mma_bf16(acc[mt][nc * 2 + 1], al[mt], bh[1], bh[3]);
                    }
                }
            }
        } else {
            // lo image: acc += Ah*Bl
            #pragma unroll
            for (int kk = 0; kk < 4; ++kk) {
                const int kg = c * 4 + kk;
                unsigned ah[2][4];
                ldsm4(ah[0], AHI + aoff + kg * 32);
                ldsm4(ah[1], AHI + aoff + 16 * Sin * 2 + kg * 32);
                #pragma unroll
                for (int nc = 0; nc < NC; ++nc) {
                    unsigned bl[4];
                    ldsm4(bl, WB + boff + nc * (16 * 144) + kk * 32);
                    #pragma unroll
                    for (int mt = 0; mt < 2; ++mt) {
                        mma_bf16(acc[mt][nc * 2 + 0], ah[mt], bl[0], bl[2]);
                        mma_bf16(acc[mt][nc * 2 + 1], ah[mt], bl[1], bl[3]);
                    }
                }
            }
        }
    }
    __syncthreads();   // all MMAs done before in-place writeback

    const int r = lane >> 2, cq = lane & 3;
    #pragma unroll
    for (int mt = 0; mt < 2; ++mt) {
        #pragma unroll
        for (int j = 0; j < N / 32; ++j) {
            const int col = n0 + j * 8 + cq * 2;
            const float b0v = bias_l[col], b1v = bias_l[col + 1];
            const int row0 = m0 + mt * 16 + r;
            float v00 = acc[mt][j][0] + b0v, v01 = acc[mt][j][1] + b1v;
            float v10 = acc[mt][j][2] + b0v, v11 = acc[mt][j][3] + b1v;
            if constexpr (SIN) {
                v00 = sinf(30.0f * v00); v01 = sinf(30.0f * v01);
                v10 = sinf(30.0f * v10); v11 = sinf(30.0f * v11);
            }
            if constexpr (!LAST) {
                __nv_bfloat162 h0 = __floats2bfloat162_rn(v00, v01);
                __nv_bfloat162 h1 = __floats2bfloat162_rn(v10, v11);
                float l00 = v00 - __bfloat162float(__low2bfloat16(h0));
                float l01 = v01 - __bfloat162float(__high2bfloat16(h0));
                float l10 = v10 - __bfloat162float(__low2bfloat16(h1));
                float l11 = v11 - __bfloat162float(__high2bfloat16(h1));
                *(u32*)(smem + 2 * (row0 * Sout + col))                 = *(u32*)&h0;
                *(u32*)(smem + 2 * ((row0 + 8) * Sout + col))           = *(u32*)&h1;
                *(u32*)(smem + ALO_OFF + 2 * (row0 * Sout + col))       = pack_bf2(l00, l01);
                *(u32*)(smem + ALO_OFF + 2 * ((row0 + 8) * Sout + col)) = pack_bf2(l10, l11);
            } else {
                float* smf = (float*)smem;   // [n][128 pixels] fp32
                smf[col * 128 + row0]           = v00;
                smf[(col + 1) * 128 + row0]     = v01;
                smf[col * 128 + row0 + 8]       = v10;
                smf[(col + 1) * 128 + row0 + 8] = v11;
            }
        }
    }
}

extern __shared__ unsigned char smem[];

__global__ __launch_bounds__(NTHR, 1)
void liif_mma_kernel(
    const float* __restrict__ feat, const float* __restrict__ times,
    const float* __restrict__ w0,
    const float* __restrict__ b0, const float* __restrict__ b1,
    const float* __restrict__ b2, const float* __restrict__ b3,
    const float* __restrict__ b4, const float* __restrict__ b5,
    float* __restrict__ out)
{
    const int tid = threadIdx.x;
    const int p0 = blockIdx.x * MTILE;
    const int bb = blockIdx.y;
    const int tt = blockIdx.z;
    const u32 sb = smem_u32(smem);
    const float tval = times[tt];

    // kick off prefetch of first stage (L0 hi, 9216 B) into buf0
    for (int i = tid * 16; i < 9216; i += NTHR * 16)
        cp16(sb + SM_W + i, g_wb + i);
    CP_COMMIT();

    // biases (time folded into b0)
    float* sbias = (float*)(smem + SM_BIAS);
    for (int i = tid; i < 960; i += NTHR) {
        float v;
        if      (i < 64)  v = b0[i] + tval * w0[i * 65 + 64];
        else if (i < 128) v = b1[i - 64];
        else if (i < 384) v = b2[i - 128];
        else if (i < 640) v = b3[i - 384];
        else if (i < 896) v = b4[i - 640];
        else              v = b5[i - 896];
        sbias[i] = v;
    }

    // feat -> A hi/lo images, stride 72 halves (identity gather)
    for (int e = tid; e < MTILE * 64; e += NTHR) {
        int c = e >> 7, p = e & 127;
        float v = feat[(size_t)(bb * 64 + c) * HW + p0 + p];
        __nv_bfloat16 h = __float2bfloat16(v);
        __nv_bfloat16 lo = __float2bfloat16(v - __bfloat162float(h));
        *(__nv_bfloat16*)(smem + 2 * (p * 72 + c))           = h;
        *(__nv_bfloat16*)(smem + ALO_OFF + 2 * (p * 72 + c)) = lo;
    }
    // (first layer stage-top does wait+sync)

    //                K    N   SIN    LAST  NEXTB (next layer first-stage bytes)
    layer_mma< 64,  64, true,  false,  9216>(smem, sb, 0,      sbias,       tid);
    layer_mma< 64,  64, true,  false, 36864>(smem, sb, 18432,  sbias + 64,  tid);
    layer_mma< 64, 256, true,  false, 36864>(smem, sb, 36864,  sbias + 128, tid);
    layer_mma<256, 256, true,  false, 36864>(smem, sb, 110592, sbias + 384, tid);
    layer_mma<256, 256, true,  false,  9216>(smem, sb, 405504, sbias + 640, tid);
    layer_mma<256,  64, false, true,      0>(smem, sb, 700416, sbias + 896, tid);

    __syncthreads();
    // coalesced store: out[(tt*2+bb)*64 + n][p0 + p]
    float* smf = (float*)smem;
    float* gout = out + (size_t)(tt * 2 + bb) * 64 * HW;
    for (int e = tid; e < 64 * 128; e += NTHR) {
        int n = e >> 7, p = e & 127;
        gout[(size_t)n * HW + p0 + p] = smf[n * 128 + p];
    }
}

extern "C" void kernel_launch(void* const* d_in, const int* in_sizes, int n_in,
                              void* d_out, int out_size) {
    const float* feat  = (const float*)d_in[0];
    const float* times = (const float*)d_in[1];
    const float* w0 = (const float*)d_in[2];
    const float* b0 = (const float*)d_in[3];
    const float* w1 = (const float*)d_in[4];
    const float* b1 = (const float*)d_in[5];
    const float* w2 = (const float*)d_in[6];
    const float* b2 = (const float*)d_in[7];
    const float* w3 = (const float*)d_in[8];
    const float* b3 = (const float*)d_in[9];
    const float* w4 = (const float*)d_in[10];
    const float* b4 = (const float*)d_in[11];
    const float* w5 = (const float*)d_in[12];
    const float* b5 = (const float*)d_in[13];
    float* out = (float*)d_out;

    prep_weights<<<(172032 + 255) / 256, 256>>>(w0, w1, w2, w3, w4, w5);

    cudaFuncSetAttribute(liif_mma_kernel,
                         cudaFuncAttributeMaxDynamicSharedMemorySize, SM_TOT);
    dim3 grid(HW / MTILE, 2, 3);   // 480 x 2 x 3 = 2880 CTAs
    liif_mma_kernel<<<grid, NTHR, SM_TOT>>>(
        feat, times, w0, b0, b1, b2, b3, b4, b5, out);
}

// round 12
// speedup vs baseline: 2.8098x; 1.0549x over previous
#include <cuda_runtime.h>
#include <cuda_bf16.h>
#include <math.h>
#include <stdint.h>

#define HW    61440
#define MTILE 64
#define NTHR  256

typedef unsigned int u32;

// Pre-split (bf16 hi/lo) weights as k32-sliced images, row stride 80 B (16-aligned).
// Per layer: [hi: K/32 stages][lo: K/32 stages], stage = N rows x 80 B.
// Layer bytes = K*N*5. Bases: L0 0, L1 20480, L2 40960, L3 122880, L4 450560,
// L5 778240, end 860160. + pad for fixed-window prefetch.
__device__ __align__(16) unsigned char g_wb[880640];

// smem layout (bytes):
//   0       A_hi image (max 64 x 264 halves = 33792)
//   33792   A_lo image (33792)
//   67584   W stage buffers: 2 x 20480
//   108544  bias[960]
#define ALO_OFF 33792
#define SM_W    67584
#define WBUF    20480
#define SM_BIAS 108544
#define SM_TOT  112384

__device__ __forceinline__ u32 smem_u32(const void* p) {
    u32 a; asm("{ .reg .u64 t; cvta.to.shared.u64 t, %1; cvt.u32.u64 %0, t; }"
               : "=r"(a) : "l"(p)); return a;
}
__device__ __forceinline__ void ldsm4(unsigned* r, u32 addr) {
    asm volatile("ldmatrix.sync.aligned.m8n8.x4.shared.b16 {%0,%1,%2,%3}, [%4];"
        : "=r"(r[0]), "=r"(r[1]), "=r"(r[2]), "=r"(r[3]) : "r"(addr));
}
__device__ __forceinline__ void mma_bf16(float* d, const unsigned* a, unsigned b0, unsigned b1) {
    asm volatile("mma.sync.aligned.m16n8k16.row.col.f32.bf16.bf16.f32 "
        "{%0,%1,%2,%3}, {%4,%5,%6,%7}, {%8,%9}, {%0,%1,%2,%3};"
        : "+f"(d[0]), "+f"(d[1]), "+f"(d[2]), "+f"(d[3])
        : "r"(a[0]), "r"(a[1]), "r"(a[2]), "r"(a[3]), "r"(b0), "r"(b1));
}
__device__ __forceinline__ void cp16(u32 dst, const void* src) {
    asm volatile("cp.async.cg.shared.global [%0], [%1], 16;" :: "r"(dst), "l"(src));
}
#define CP_COMMIT() asm volatile("cp.async.commit_group;" ::: "memory")
#define CP_WAIT0()  asm volatile("cp.async.wait_group 0;" ::: "memory")

__device__ __forceinline__ u32 pack_bf2(float v0, float v1) {
    __nv_bfloat162 h = __floats2bfloat162_rn(v0, v1);
    return *(u32*)&h;
}

// ---------- weight prep ----------
__global__ void prep_weights(
    const float* __restrict__ w0, const float* __restrict__ w1,
    const float* __restrict__ w2, const float* __restrict__ w3,
    const float* __restrict__ w4, const float* __restrict__ w5)
{
    int i = blockIdx.x * blockDim.x + threadIdx.x;
    if (i >= 172032) return;
    const float* w; int j, K, N, ldw; u32 base;
    if      (i < 4096)   { j = i;          w = w0; K = 64;  N = 64;  ldw = 65;  base = 0; }
    else if (i < 8192)   { j = i - 4096;   w = w1; K = 64;  N = 64;  ldw = 64;  base = 20480; }
    else if (i < 24576)  { j = i - 8192;   w = w2; K = 64;  N = 256; ldw = 64;  base = 40960; }
    else if (i < 90112)  { j = i - 24576;  w = w3; K = 256; N = 256; ldw = 256; base = 122880; }
    else if (i < 155648) { j = i - 90112;  w = w4; K = 256; N = 256; ldw = 256; base = 450560; }
    else                 { j = i - 155648; w = w5; K = 256; N = 64;  ldw = 256; base = 778240; }
    int n = j / K, k = j % K;
    float v = w[n * ldw + k];
    __nv_bfloat16 h = __float2bfloat16(v);
    __nv_bfloat16 lo = __float2bfloat16(v - __bfloat162float(h));
    u32 half_img = (u32)(K / 32) * (u32)N * 80u;
    u32 dst = base + (u32)(k >> 5) * ((u32)N * 80u) + (u32)n * 80u + (u32)(k & 31) * 2u;
    *(__nv_bfloat16*)(g_wb + dst)            = h;
    *(__nv_bfloat16*)(g_wb + dst + half_img) = lo;
}

// ---------- per-layer GEMM, 2-deep cp.async pipeline over k32 stages ----------
// D[64 x N] = A[64 x K] @ W^T, 3-term bf16 split, in-place activation update.
// 8 warps: wm=wid&1 -> m0=wm*32; wc=wid>>1 -> n0=wc*(N/4).
template<int K, int N, bool SIN, bool LAST, int NEXTB>
__device__ __forceinline__ void layer_mma(
    unsigned char* smem, u32 sb, u32 wbase, const float* bias_l, int tid)
{
    constexpr int Sin = K + 8;     // halves
    constexpr int Sout = N + 8;
    constexpr int NC  = N / 64;    // n16 chunks per warp
    constexpr int CH2 = K / 32;    // k32 stages per image
    constexpr int STB = N * 80;    // stage bytes

    const int lane = tid & 31, wid = tid >> 5;
    const int m0 = (wid & 1) * 32;
    const int n0 = (wid >> 1) * (N / 4);

    float acc[2][N / 32][4];
    #pragma unroll
    for (int mt = 0; mt < 2; ++mt)
        #pragma unroll
        for (int j = 0; j < N / 32; ++j)
            #pragma unroll
            for (int q = 0; q < 4; ++q) acc[mt][j][q] = 0.0f;

    const int koff8 = (lane & 16) ? 8 : 0;
    const u32 AHI = sb;
    const u32 ALO = sb + ALO_OFF;
    const u32 aoff = (u32)(((m0 + (lane & 15)) * Sin + koff8) * 2);
    const u32 boff = (u32)(((n0 + (lane & 15)) * 40 + koff8) * 2);   // 80 B rows

    // ---- hi stages: acc += Ah*Bh + Al*Bh over k in [32s, 32s+32) ----
    #pragma unroll 2
    for (int st = 0; st < CH2; ++st) {
        CP_WAIT0();
        __syncthreads();
        {   // prefetch next stage (next hi, or first lo — contiguous, same size)
            const unsigned char* src = g_wb + wbase + (size_t)(st + 1) * STB;
            u32 dst = sb + SM_W + (u32)(((st + 1) & 1) * WBUF);
            for (int i = tid * 16; i < STB; i += NTHR * 16) cp16(dst + i, src + i);
            CP_COMMIT();
        }
        const u32 WB = sb + SM_W + (u32)((st & 1) * WBUF);
        #pragma unroll
        for (int kk = 0; kk < 2; ++kk) {
            const int kg = st * 2 + kk;
            unsigned ah[2][4], al[2][4];
            ldsm4(ah[0], AHI + aoff + kg * 32);
            ldsm4(ah[1], AHI + aoff + 16 * Sin * 2 + kg * 32);
            ldsm4(al[0], ALO + aoff + kg * 32);
            ldsm4(al[1], ALO + aoff + 16 * Sin * 2 + kg * 32);
            #pragma unroll
            for (int nc = 0; nc < NC; ++nc) {
                unsigned bh[4];
                ldsm4(bh, WB + boff + nc * (16 * 80) + kk * 32);
                #pragma unroll
                for (int mt = 0; mt < 2; ++mt) {
                    mma_bf16(acc[mt][nc * 2 + 0], ah[mt], bh[0], bh[2]);
                    mma_bf16(acc[mt][nc * 2 + 1], ah[mt], bh[1], bh[3]);
                    mma_bf16(acc[mt][nc * 2 + 0], al[mt], bh[0], bh[2]);
                    mma_bf16(acc[mt][nc * 2 + 1], al[mt], bh[1], bh[3]);
                }
            }
        }
    }

    // ---- lo stages: acc += Ah*Bl ----
    #pragma unroll 2
    for (int s = 0; s < CH2; ++s) {
        const int st = CH2 + s;
        CP_WAIT0();
        __syncthreads();
        {
            const int nb = (s + 1 < CH2) ? STB : NEXTB;
            if (nb > 0) {
                const unsigned char* src = g_wb + wbase + (size_t)(st + 1) * STB;
                u32 dst = sb + SM_W + (u32)(((st + 1) & 1) * WBUF);
                for (int i = tid * 16; i < nb; i += NTHR * 16) cp16(dst + i, src + i);
            }
            CP_COMMIT();
        }
        const u32 WB = sb + SM_W + (u32)((st & 1) * WBUF);
        #pragma unroll
        for (int kk = 0; kk < 2; ++kk) {
            const int kg = s * 2 + kk;
            unsigned ah[2][4];
            ldsm4(ah[0], AHI + aoff + kg * 32);
            ldsm4(ah[1], AHI + aoff + 16 * Sin * 2 + kg * 32);
            #pragma unroll
            for (int nc = 0; nc < NC; ++nc) {
                unsigned bl[4];
                ldsm4(bl, WB + boff + nc * (16 * 80) + kk * 32);
                #pragma unroll
                for (int mt = 0; mt < 2; ++mt) {
                    mma_bf16(acc[mt][nc * 2 + 0], ah[mt], bl[0], bl[2]);
                    mma_bf16(acc[mt][nc * 2 + 1], ah[mt], bl[1], bl[3]);
                }
            }
        }
    }
    __syncthreads();   // all MMAs done before in-place writeback

    const int r = lane >> 2, cq = lane & 3;
    #pragma unroll
    for (int mt = 0; mt < 2; ++mt) {
        #pragma unroll
        for (int j = 0; j < N / 32; ++j) {
            const int col = n0 + j * 8 + cq * 2;
            const float b0v = bias_l[col], b1v = bias_l[col + 1];
            const int row0 = m0 + mt * 16 + r;
            float v00 = acc[mt][j][0] + b0v, v01 = acc[mt][j][1] + b1v;
            float v10 = acc[mt][j][2] + b0v, v11 = acc[mt][j][3] + b1v;
            if constexpr (SIN) {
                v00 = sinf(30.0f * v00); v01 = sinf(30.0f * v01);
                v10 = sinf(30.0f * v10); v11 = sinf(30.0f * v11);
            }
            if constexpr (!LAST) {
                __nv_bfloat162 h0 = __floats2bfloat162_rn(v00, v01);
                __nv_bfloat162 h1 = __floats2bfloat162_rn(v10, v11);
                float l00 = v00 - __bfloat162float(__low2bfloat16(h0));
                float l01 = v01 - __bfloat162float(__high2bfloat16(h0));
                float l10 = v10 - __bfloat162float(__low2bfloat16(h1));
                float l11 = v11 - __bfloat162float(__high2bfloat16(h1));
                *(u32*)(smem + 2 * (row0 * Sout + col))                 = *(u32*)&h0;
                *(u32*)(smem + 2 * ((row0 + 8) * Sout + col))           = *(u32*)&h1;
                *(u32*)(smem + ALO_OFF + 2 * (row0 * Sout + col))       = pack_bf2(l00, l01);
                *(u32*)(smem + ALO_OFF + 2 * ((row0 + 8) * Sout + col)) = pack_bf2(l10, l11);
            } else {
                float* smf = (float*)smem;   // [n][64 pixels] fp32
                smf[col * 64 + row0]           = v00;
                smf[(col + 1) * 64 + row0]     = v01;
                smf[col * 64 + row0 + 8]       = v10;
                smf[(col + 1) * 64 + row0 + 8] = v11;
            }
        }
    }
}

extern __shared__ unsigned char smem[];

__global__ __launch_bounds__(NTHR, 2)
void liif_mma_kernel(
    const float* __restrict__ feat, const float* __restrict__ times,
    const float* __restrict__ w0,
    const float* __restrict__ b0, const float* __restrict__ b1,
    const float* __restrict__ b2, const float* __restrict__ b3,
    const float* __restrict__ b4, const float* __restrict__ b5,
    float* __restrict__ out)
{
    const int tid = threadIdx.x;
    const int p0 = blockIdx.x * MTILE;
    const int bb = blockIdx.y;
    const int tt = blockIdx.z;
    const u32 sb = smem_u32(smem);
    const float tval = times[tt];

    // prefetch first stage (L0 hi s=0: 64*80 = 5120 B) into buf0
    for (int i = tid * 16; i < 5120; i += NTHR * 16)
        cp16(sb + SM_W + i, g_wb + i);
    CP_COMMIT();

    // biases (time folded into b0)
    float* sbias = (float*)(smem + SM_BIAS);
    for (int i = tid; i < 960; i += NTHR) {
        float v;
        if      (i < 64)  v = b0[i] + tval * w0[i * 65 + 64];
        else if (i < 128) v = b1[i - 64];
        else if (i < 384) v = b2[i - 128];
        else if (i < 640) v = b3[i - 384];
        else if (i < 896) v = b4[i - 640];
        else              v = b5[i - 896];
        sbias[i] = v;
    }

    // feat -> A hi/lo images, stride 72 halves (identity gather)
    for (int e = tid; e < MTILE * 64; e += NTHR) {
        int c = e >> 6, p = e & 63;
        float v = feat[(size_t)(bb * 64 + c) * HW + p0 + p];
        __nv_bfloat16 h = __float2bfloat16(v);
        __nv_bfloat16 lo = __float2bfloat16(v - __bfloat162float(h));
        *(__nv_bfloat16*)(smem + 2 * (p * 72 + c))           = h;
        *(__nv_bfloat16*)(smem + ALO_OFF + 2 * (p * 72 + c)) = lo;
    }
    // (first layer stage-top does wait+sync)

    //                K    N   SIN    LAST  NEXTB (next layer first-stage bytes = N_next*80)
    layer_mma< 64,  64, true,  false,  5120>(smem, sb, 0,      sbias,       tid);
    layer_mma< 64,  64, true,  false, 20480>(smem, sb, 20480,  sbias + 64,  tid);
    layer_mma< 64, 256, true,  false, 20480>(smem, sb, 40960,  sbias + 128, tid);
    layer_mma<256, 256, true,  false, 20480>(smem, sb, 122880, sbias + 384, tid);
    layer_mma<256, 256, true,  false,  5120>(smem, sb, 450560, sbias + 640, tid);
    layer_mma<256,  64, false, true,      0>(smem, sb, 778240, sbias + 896, tid);

    __syncthreads();
    // coalesced store: out[(tt*2+bb)*64 + n][p0 + p]
    float* smf = (float*)smem;
    float* gout = out + (size_t)(tt * 2 + bb) * 64 * HW;
    for (int e = tid; e < 64 * MTILE; e += NTHR) {
        int n = e >> 6, p = e & 63;
        gout[(size_t)n * HW + p0 + p] = smf[n * 64 + p];
    }
}

extern "C" void kernel_launch(void* const* d_in, const int* in_sizes, int n_in,
                              void* d_out, int out_size) {
    const float* feat  = (const float*)d_in[0];
    const float* times = (const float*)d_in[1];
    const float* w0 = (const float*)d_in[2];
    const float* b0 = (const float*)d_in[3];
    const float* w1 = (const float*)d_in[4];
    const float* b1 = (const float*)d_in[5];
    const float* w2 = (const float*)d_in[6];
    const float* b2 = (const float*)d_in[7];
    const float* w3 = (const float*)d_in[8];
    const float* b3 = (const float*)d_in[9];
    const float* w4 = (const float*)d_in[10];
    const float* b4 = (const float*)d_in[11];
    const float* w5 = (const float*)d_in[12];
    const float* b5 = (const float*)d_in[13];
    float* out = (float*)d_out;

    prep_weights<<<(172032 + 255) / 256, 256>>>(w0, w1, w2, w3, w4, w5);

    cudaFuncSetAttribute(liif_mma_kernel,
                         cudaFuncAttributeMaxDynamicSharedMemorySize, SM_TOT);
    dim3 grid(HW / MTILE, 2, 3);   // 960 x 2 x 3 = 5760 CTAs, 2 per SM
    liif_mma_kernel<<<grid, NTHR, SM_TOT>>>(
        feat, times, w0, b0, b1, b2, b3, b4, b5, out);
}